// round 13
// baseline (speedup 1.0000x reference)
#include <cuda_runtime.h>
#include <cuda_bf16.h>
#include <cstdint>

// LSTM B=4096,T=512,IN=1,H=32,OUT=1 — bf16 m16n8k16, fp32 accum/cell.
// R13: FULLY WARP-LOCAL. One warp owns 8 batch elems and ALL 128 gate-rows
// (8 m-tiles, 16 HMMAs/step). No __syncthreads in the time loop — h exchange
// is per-warp smem with one __syncwarp/step (double-buffered). Each thread's
// epilogue: 8 cells (j=gid+8r, n=2lq+dc), i/f/g/o all register-local.
// 128 CTAs x 128 thr (4 independent warps/CTA, 1 warp/SMSP).

#define TT  512
#define HH  32
#define BB  4096

typedef unsigned long long u64;

__device__ __forceinline__ uint32_t pack_bf16(float lo, float hi) {
    uint32_t r;                        // first asm src -> upper half
    asm("cvt.rn.bf16x2.f32 %0, %1, %2;" : "=r"(r) : "f"(hi), "f"(lo));
    return r;
}
__device__ __forceinline__ float tanh_hw(float x) {
    float r;
    asm("tanh.approx.f32 %0, %1;" : "=f"(r) : "f"(x));
    return r;
}
__device__ __forceinline__ void mma_bf16(float* d, const uint32_t* a,
                                         const uint32_t* b) {
    asm volatile(
        "mma.sync.aligned.m16n8k16.row.col.f32.bf16.bf16.f32 "
        "{%0,%1,%2,%3}, {%4,%5,%6,%7}, {%8,%9}, {%0,%1,%2,%3};"
        : "+f"(d[0]), "+f"(d[1]), "+f"(d[2]), "+f"(d[3])
        : "r"(a[0]), "r"(a[1]), "r"(a[2]), "r"(a[3]), "r"(b[0]), "r"(b[1]));
}

// Per-warp h buffer: 128 u32 words, word(kp, n) = kp*8 + n, packing
// {h[k=2kp][n] (lo 16b), h[2kp+1][n] (hi)} as bf16. B fragment (kt):
//   bf[kt][0] = word (lq+8kt)*8+gid   (k = 2lq+16kt, +1)
//   bf[kt][1] = word (lq+4+8kt)*8+gid (k = 2lq+8+16kt, +1)   — conflict-free.

__global__ __launch_bounds__(128, 1)
void lstm_wl_kernel(const float* __restrict__ x,      // [B,T]
                    const float* __restrict__ W_ih,   // [4H]
                    const float* __restrict__ W_hh,   // [4H,H]
                    const float* __restrict__ b_ih,   // [4H]
                    const float* __restrict__ b_hh,   // [4H]
                    const float* __restrict__ fc_w,   // [H]
                    const float* __restrict__ fc_b,   // [1]
                    float* __restrict__ out)          // [B]
{
    __shared__ __align__(16) uint32_t hbuf[4][2][128];  // per-warp, 2 buffers
    __shared__ __align__(16) float    xs[4][64][8];     // per-warp x chunk [t][n]

    const int tid = threadIdx.x;
    const int w   = tid >> 5;
    const int l   = tid & 31;
    const int gid = l >> 2;            // 0..7
    const int lq  = l & 3;             // 0..3
    const int b0  = (blockIdx.x * 4 + w) * 8;

    // A fragments: G-row m == W_hh row m (gate-major). Tile mt covers rows
    // [16mt,16mt+16), gate g = mt>>1; sigmoid gates scaled x0.5.
    uint32_t af[8][2][4];
    float    wih2[8][2], bias2[8][2];
    #pragma unroll
    for (int mt = 0; mt < 8; mt++) {
        const float s  = ((mt >> 1) == 2) ? 1.0f : 0.5f;
        const int   r0 = 16 * mt + gid, r1 = r0 + 8;
        const float* p0 = W_hh + r0 * HH;
        const float* p1 = W_hh + r1 * HH;
        #pragma unroll
        for (int kt = 0; kt < 2; kt++) {
            const int k0 = 16 * kt + 2 * lq;
            af[mt][kt][0] = pack_bf16(p0[k0] * s,     p0[k0 + 1] * s);
            af[mt][kt][1] = pack_bf16(p1[k0] * s,     p1[k0 + 1] * s);
            af[mt][kt][2] = pack_bf16(p0[k0 + 8] * s, p0[k0 + 9] * s);
            af[mt][kt][3] = pack_bf16(p1[k0 + 8] * s, p1[k0 + 9] * s);
        }
        wih2[mt][0]  = W_ih[r0] * s;
        wih2[mt][1]  = W_ih[r1] * s;
        bias2[mt][0] = (b_ih[r0] + b_hh[r0]) * s;
        bias2[mt][1] = (b_ih[r1] + b_hh[r1]) * s;
    }

    // zero h_0 (buffer 0)
    #pragma unroll
    for (int i = 0; i < 4; i++) hbuf[w][0][l + 32 * i] = 0u;

    // hoisted addresses
    const uint32_t* ldp[2] = { &hbuf[w][0][lq * 8 + gid],
                               &hbuf[w][1][lq * 8 + gid] };
    const int stw = ((gid >> 1) * 8 + 2 * lq) * 2 + (gid & 1);   // u16 index
    uint16_t* stp[2] = { reinterpret_cast<uint16_t*>(hbuf[w][0]) + stw,
                         reinterpret_cast<uint16_t*>(hbuf[w][1]) + stw };
    // offsets: dc -> +2 u16 ; r -> +64 u16

    float c[8], hl[8];
    #pragma unroll
    for (int q = 0; q < 8; q++) { c[q] = 0.0f; hl[q] = 0.0f; }

    #pragma unroll 1
    for (int tb = 0; tb < TT; tb += 2) {
        if ((tb & 63) == 0) {
            // per-warp x refill: lane covers elem n=l>>2, 16 steps
            const int n = l >> 2, p4 = l & 3;
            const float4* src = reinterpret_cast<const float4*>(
                x + (size_t)(b0 + n) * TT + tb + p4 * 16);
            #pragma unroll
            for (int i = 0; i < 4; i++) {
                const float4 v = src[i];
                const int t0 = p4 * 16 + i * 4;
                xs[w][t0 + 0][n] = v.x;
                xs[w][t0 + 1][n] = v.y;
                xs[w][t0 + 2][n] = v.z;
                xs[w][t0 + 3][n] = v.w;
            }
            __syncwarp();
        }

        #pragma unroll
        for (int ph = 0; ph < 2; ph++) {
            const int t = tb + ph;
            const int p = ph;              // tb even -> read buf p, write p^1

            // acc init: fold x*W_ih + bias (32 FMAs, fma pipe has headroom)
            const float2 xv =
                *reinterpret_cast<const float2*>(&xs[w][t & 63][2 * lq]);
            float acc[8][4];
            #pragma unroll
            for (int mt = 0; mt < 8; mt++) {
                acc[mt][0] = fmaf(xv.x, wih2[mt][0], bias2[mt][0]);
                acc[mt][1] = fmaf(xv.y, wih2[mt][0], bias2[mt][0]);
                acc[mt][2] = fmaf(xv.x, wih2[mt][1], bias2[mt][1]);
                acc[mt][3] = fmaf(xv.y, wih2[mt][1], bias2[mt][1]);
            }

            // B fragments (4 conflict-free LDS.32)
            uint32_t bf[2][2];
            bf[0][0] = ldp[p][0];
            bf[0][1] = ldp[p][32];
            bf[1][0] = ldp[p][64];
            bf[1][1] = ldp[p][96];

            // 16 HMMAs: 8 independent chains of depth 2
            #pragma unroll
            for (int mt = 0; mt < 8; mt++) {
                mma_bf16(acc[mt], af[mt][0], bf[0]);
                mma_bf16(acc[mt], af[mt][1], bf[1]);
            }

            // epilogue: 8 register-local cells (j = gid+8r, n = 2lq+dc)
            #pragma unroll
            for (int r = 0; r < 4; r++) {
                const int rh = r >> 1, rl = 2 * (r & 1);
                #pragma unroll
                for (int dc = 0; dc < 2; dc++) {
                    const int q = 2 * r + dc;
                    const float pi = acc[0 + rh][rl + dc];
                    const float pf = acc[2 + rh][rl + dc];
                    const float pg = acc[4 + rh][rl + dc];
                    const float po = acc[6 + rh][rl + dc];
                    const float gi = fmaf(0.5f, tanh_hw(pi), 0.5f);
                    const float gf = fmaf(0.5f, tanh_hw(pf), 0.5f);
                    const float gg = tanh_hw(pg);
                    const float go = fmaf(0.5f, tanh_hw(po), 0.5f);
                    c[q] = fmaf(gf, c[q], gi * gg);
                    const float h = go * tanh_hw(c[q]);
                    hl[q] = h;
                    __nv_bfloat16 hb = __float2bfloat16(h);
                    stp[p ^ 1][r * 64 + dc * 2] = *reinterpret_cast<uint16_t*>(&hb);
                }
            }
            __syncwarp();   // h writes visible before next step's B loads
        }
    }

    // out[n] = dot(h[:,n], fc_w) + fc_b ; reduce over gid (lanes stride 4)
    float v0 = 0.0f, v1 = 0.0f;
    #pragma unroll
    for (int r = 0; r < 4; r++) {
        const float fw = fc_w[gid + 8 * r];
        v0 = fmaf(hl[2 * r + 0], fw, v0);
        v1 = fmaf(hl[2 * r + 1], fw, v1);
    }
    #pragma unroll
    for (int off = 4; off < 32; off <<= 1) {
        v0 += __shfl_xor_sync(0xffffffffu, v0, off);
        v1 += __shfl_xor_sync(0xffffffffu, v1, off);
    }
    if (gid == 0) {
        out[b0 + 2 * lq]     = v0 + fc_b[0];
        out[b0 + 2 * lq + 1] = v1 + fc_b[0];
    }
}

extern "C" void kernel_launch(void* const* d_in, const int* in_sizes, int n_in,
                              void* d_out, int out_size) {
    const float* x    = (const float*)d_in[0];
    const float* W_ih = (const float*)d_in[1];
    const float* W_hh = (const float*)d_in[2];
    const float* b_ih = (const float*)d_in[3];
    const float* b_hh = (const float*)d_in[4];
    const float* fc_w = (const float*)d_in[5];
    const float* fc_b = (const float*)d_in[6];
    float* out = (float*)d_out;

    // 4096 elems / (4 warps x 8 elems) = 128 CTAs; warps fully independent.
    lstm_wl_kernel<<<BB / 32, 128>>>(x, W_ih, W_hh, b_ih, b_hh, fc_w, fc_b, out);
}

// round 14
// speedup vs baseline: 1.0028x; 1.0028x over previous
#include <cuda_runtime.h>
#include <cuda_bf16.h>
#include <cstdint>

// LSTM B=4096,T=512,IN=1,H=32,OUT=1 — bf16 m16n8k16 mma.sync, fp32 accum/cell.
// R14: R11 + TWO independent 8-elem groups per CTA (NB=16, grid=256).
// Each warp carries two independent per-step chains (A,B) in one instruction
// stream -> deterministic latency overlap (vs arbiter-dependent cross-CTA
// interleave). One __syncthreads per step now covers 16 elements.
// Warp w owns hidden units [8w,8w+8) of ALL 4 gates for both groups.

#define TT  512
#define HH  32
#define BB  4096
#define NB  16     // 2 groups x 8

typedef unsigned long long u64;

__device__ __forceinline__ uint32_t pack_bf16(float lo, float hi) {
    uint32_t r;                        // first asm src -> upper half
    asm("cvt.rn.bf16x2.f32 %0, %1, %2;" : "=r"(r) : "f"(hi), "f"(lo));
    return r;
}
__device__ __forceinline__ float tanh_hw(float x) {
    float r;
    asm("tanh.approx.f32 %0, %1;" : "=f"(r) : "f"(x));
    return r;
}
__device__ __forceinline__ void mma_bf16(float* d, const uint32_t* a,
                                         const uint32_t* b) {
    asm volatile(
        "mma.sync.aligned.m16n8k16.row.col.f32.bf16.bf16.f32 "
        "{%0,%1,%2,%3}, {%4,%5,%6,%7}, {%8,%9}, {%0,%1,%2,%3};"
        : "+f"(d[0]), "+f"(d[1]), "+f"(d[2]), "+f"(d[3])
        : "r"(a[0]), "r"(a[1]), "r"(a[2]), "r"(a[3]), "r"(b[0]), "r"(b[1]));
}

// Per-group h layout identical to R11 (128 u32 words of bf16x2):
// word(n,kp): kt=kp>>3,r=(kp>>2)&1,lqk=kp&3 -> kt*64 + lqk*16 + n*2 + r.
// B fragment (kt) = LDS.64 at word kt*64 + lq*16 + gid*2.

__global__ __launch_bounds__(128, 2)
void lstm_g2_kernel(const float* __restrict__ x,      // [B,T]
                    const float* __restrict__ W_ih,   // [4H]
                    const float* __restrict__ W_hh,   // [4H,H]
                    const float* __restrict__ b_ih,   // [4H]
                    const float* __restrict__ b_hh,   // [4H]
                    const float* __restrict__ fc_w,   // [H]
                    const float* __restrict__ fc_b,   // [1]
                    float* __restrict__ out)          // [B]
{
    __shared__ __align__(16) uint32_t hbuf[2][2][128];  // [buf][grp][word]
    __shared__ __align__(16) float    xs[64][NB];       // x chunk [t][n]

    const int tid = threadIdx.x;
    const int w   = tid >> 5;
    const int l   = tid & 31;
    const int gid = l >> 2;            // 0..7
    const int lq  = l & 3;             // 0..3
    const int b0  = blockIdx.x * NB;
    const int j   = 8 * w + gid;       // hidden unit owned in epilogue

    // A fragments (persistent, shared by both groups); sigmoid gates x0.5.
    uint32_t af[2][2][4];
    #pragma unroll
    for (int mt = 0; mt < 2; mt++) {
        const int g0 = 2 * mt, g1 = 2 * mt + 1;
        const float s0 = (g0 == 2) ? 1.0f : 0.5f;
        const float s1 = (g1 == 2) ? 1.0f : 0.5f;
        const float* r0 = W_hh + (g0 * HH + j) * HH;
        const float* r1 = W_hh + (g1 * HH + j) * HH;
        #pragma unroll
        for (int kt = 0; kt < 2; kt++) {
            const int k0 = kt * 16 + 2 * lq;
            af[mt][kt][0] = pack_bf16(r0[k0] * s0,     r0[k0 + 1] * s0);
            af[mt][kt][1] = pack_bf16(r1[k0] * s1,     r1[k0 + 1] * s1);
            af[mt][kt][2] = pack_bf16(r0[k0 + 8] * s0, r0[k0 + 9] * s0);
            af[mt][kt][3] = pack_bf16(r1[k0 + 8] * s1, r1[k0 + 9] * s1);
        }
    }

    float wih[4], bias[4];
    #pragma unroll
    for (int g = 0; g < 4; g++) {
        const float sc = (g == 2) ? 1.0f : 0.5f;
        wih[g]  = W_ih[g * HH + j] * sc;
        bias[g] = (b_ih[g * HH + j] + b_hh[g * HH + j]) * sc;
    }

    // h_0 = 0 for both groups (buffer 0)
    hbuf[0][0][tid] = 0u;
    hbuf[0][1][tid] = 0u;

    // Hoisted addresses: [buf][grp]
    const uint32_t* bfp[2][2];
    uint16_t*       stp[2][2];
    const int ldw = lq * 16 + gid * 2;
    const int stw = (j >> 4) * 64 + ((j >> 1) & 3) * 16 + (2 * lq) * 2 + ((j >> 3) & 1);
    const int sth = (j & 1);
    #pragma unroll
    for (int pb = 0; pb < 2; pb++)
        #pragma unroll
        for (int gg = 0; gg < 2; gg++) {
            bfp[pb][gg] = &hbuf[pb][gg][ldw];
            stp[pb][gg] = reinterpret_cast<uint16_t*>(&hbuf[pb][gg][stw]) + sth;
        }

    float cA0 = 0.f, cA1 = 0.f, cB0 = 0.f, cB1 = 0.f;

    #pragma unroll 1
    for (int tb = 0; tb < TT; tb += 2) {
        if ((tb & 63) == 0) {
            // refill x chunk [tb, tb+64): thread (n = tid>>3, part = tid&7)
            const int n = tid >> 3, part = tid & 7;
            const float4* src = reinterpret_cast<const float4*>(
                x + (size_t)(b0 + n) * TT + tb + part * 8);
            const float4 v0 = src[0], v1 = src[1];
            const int t0 = part * 8;
            xs[t0 + 0][n] = v0.x; xs[t0 + 1][n] = v0.y;
            xs[t0 + 2][n] = v0.z; xs[t0 + 3][n] = v0.w;
            xs[t0 + 4][n] = v1.x; xs[t0 + 5][n] = v1.y;
            xs[t0 + 6][n] = v1.z; xs[t0 + 7][n] = v1.w;
            __syncthreads();
        }

        #pragma unroll
        for (int ph = 0; ph < 2; ph++) {
            const int t = tb + ph;
            const int p = ph;                  // tb even -> parity == ph

            // B fragments for BOTH groups first (latency overlap)
            uint32_t bfA[2][2], bfB[2][2];
            #pragma unroll
            for (int kt = 0; kt < 2; kt++) {
                const u64 va = *reinterpret_cast<const u64*>(bfp[p][0] + kt * 64);
                const u64 vb = *reinterpret_cast<const u64*>(bfp[p][1] + kt * 64);
                bfA[kt][0] = (uint32_t)va; bfA[kt][1] = (uint32_t)(va >> 32);
                bfB[kt][0] = (uint32_t)vb; bfB[kt][1] = (uint32_t)(vb >> 32);
            }

            // acc init: fold x*W_ih + bias per group
            const float2 xvA = *reinterpret_cast<const float2*>(&xs[t & 63][2 * lq]);
            const float2 xvB = *reinterpret_cast<const float2*>(&xs[t & 63][8 + 2 * lq]);
            float accA[2][4], accB[2][4];
            #pragma unroll
            for (int mt = 0; mt < 2; mt++) {
                accA[mt][0] = fmaf(xvA.x, wih[2 * mt],     bias[2 * mt]);
                accA[mt][1] = fmaf(xvA.y, wih[2 * mt],     bias[2 * mt]);
                accA[mt][2] = fmaf(xvA.x, wih[2 * mt + 1], bias[2 * mt + 1]);
                accA[mt][3] = fmaf(xvA.y, wih[2 * mt + 1], bias[2 * mt + 1]);
                accB[mt][0] = fmaf(xvB.x, wih[2 * mt],     bias[2 * mt]);
                accB[mt][1] = fmaf(xvB.y, wih[2 * mt],     bias[2 * mt]);
                accB[mt][2] = fmaf(xvB.x, wih[2 * mt + 1], bias[2 * mt + 1]);
                accB[mt][3] = fmaf(xvB.y, wih[2 * mt + 1], bias[2 * mt + 1]);
            }

            // MMAs interleaved: 4 independent chains of depth 2
            #pragma unroll
            for (int mt = 0; mt < 2; mt++) {
                mma_bf16(accA[mt], af[mt][0], bfA[0]);
                mma_bf16(accB[mt], af[mt][0], bfB[0]);
                mma_bf16(accA[mt], af[mt][1], bfA[1]);
                mma_bf16(accB[mt], af[mt][1], bfB[1]);
            }

            // Epilogues (independent chains; compiler interleaves MUFUs)
            {
                const float gi0 = fmaf(0.5f, tanh_hw(accA[0][0]), 0.5f);
                const float gi1 = fmaf(0.5f, tanh_hw(accA[0][1]), 0.5f);
                const float gf0 = fmaf(0.5f, tanh_hw(accA[0][2]), 0.5f);
                const float gf1 = fmaf(0.5f, tanh_hw(accA[0][3]), 0.5f);
                const float gg0 =             tanh_hw(accA[1][0]);
                const float gg1 =             tanh_hw(accA[1][1]);
                const float go0 = fmaf(0.5f, tanh_hw(accA[1][2]), 0.5f);
                const float go1 = fmaf(0.5f, tanh_hw(accA[1][3]), 0.5f);
                cA0 = fmaf(gf0, cA0, gi0 * gg0);
                cA1 = fmaf(gf1, cA1, gi1 * gg1);
                const float h0 = go0 * tanh_hw(cA0);
                const float h1 = go1 * tanh_hw(cA1);
                __nv_bfloat16 hb0 = __float2bfloat16(h0);
                __nv_bfloat16 hb1 = __float2bfloat16(h1);
                stp[p ^ 1][0][0] = *reinterpret_cast<uint16_t*>(&hb0);
                stp[p ^ 1][0][4] = *reinterpret_cast<uint16_t*>(&hb1);
            }
            {
                const float gi0 = fmaf(0.5f, tanh_hw(accB[0][0]), 0.5f);
                const float gi1 = fmaf(0.5f, tanh_hw(accB[0][1]), 0.5f);
                const float gf0 = fmaf(0.5f, tanh_hw(accB[0][2]), 0.5f);
                const float gf1 = fmaf(0.5f, tanh_hw(accB[0][3]), 0.5f);
                const float gg0 =             tanh_hw(accB[1][0]);
                const float gg1 =             tanh_hw(accB[1][1]);
                const float go0 = fmaf(0.5f, tanh_hw(accB[1][2]), 0.5f);
                const float go1 = fmaf(0.5f, tanh_hw(accB[1][3]), 0.5f);
                cB0 = fmaf(gf0, cB0, gi0 * gg0);
                cB1 = fmaf(gf1, cB1, gi1 * gg1);
                const float h0 = go0 * tanh_hw(cB0);
                const float h1 = go1 * tanh_hw(cB1);
                __nv_bfloat16 hb0 = __float2bfloat16(h0);
                __nv_bfloat16 hb1 = __float2bfloat16(h1);
                stp[p ^ 1][1][0] = *reinterpret_cast<uint16_t*>(&hb0);
                stp[p ^ 1][1][4] = *reinterpret_cast<uint16_t*>(&hb1);
            }

            __syncthreads();
        }
    }

    // out[n] = dot(h[n,:], fc_w) + fc_b   (final h in hbuf[0]: T even)
    if (tid < NB) {
        const int n  = tid;
        const int gg = n >> 3, nn = n & 7;
        const uint16_t* hb16 = reinterpret_cast<const uint16_t*>(hbuf[0][gg]);
        float s = fc_b[0];
        #pragma unroll
        for (int k = 0; k < HH; k++) {
            const int word = (k >> 4) * 64 + ((k >> 1) & 3) * 16 + nn * 2 + ((k >> 3) & 1);
            const uint16_t bits = hb16[word * 2 + (k & 1)];
            __nv_bfloat16 hv = *reinterpret_cast<const __nv_bfloat16*>(&bits);
            s = fmaf(__bfloat162float(hv), fc_w[k], s);
        }
        out[b0 + n] = s;
    }
}

extern "C" void kernel_launch(void* const* d_in, const int* in_sizes, int n_in,
                              void* d_out, int out_size) {
    const float* x    = (const float*)d_in[0];
    const float* W_ih = (const float*)d_in[1];
    const float* W_hh = (const float*)d_in[2];
    const float* b_ih = (const float*)d_in[3];
    const float* b_hh = (const float*)d_in[4];
    const float* fc_w = (const float*)d_in[5];
    const float* fc_b = (const float*)d_in[6];
    float* out = (float*)d_out;

    lstm_g2_kernel<<<BB / NB, 128>>>(x, W_ih, W_hh, b_ih, b_hh, fc_w, fc_b, out);
}